// round 2
// baseline (speedup 1.0000x reference)
#include <cuda_runtime.h>
#include <cfloat>

#define NPTS 1024
#define BATCH 8
#define DIN 60
#define DPAD 64
#define KNN 20
#define P1 (BATCH*NPTS*KNN)   /* 163840 */
#define P2 (BATCH*NPTS)       /* 8192 */
#define BN_EPS 1e-5f
#define SLOPE 0.2f

// ---------------- scratch (device globals; no runtime alloc) ----------------
__device__ float g_xt[BATCH*NPTS*DPAD];       // point-major x, padded to 64
__device__ float g_xx[BATCH*NPTS];            // squared norms
__device__ int   g_idx[BATCH*NPTS*KNN];       // knn indices
__device__ float g_f0[P1*128];                // graph features (padded 120->128)
__device__ float g_w1p[64*128];               // padded w1
__device__ float g_h1[P1*64];
__device__ float g_h2[P1*64];
__device__ float g_h3[P1*128];
__device__ float g_h4[P1*256];
__device__ float g_xc[P2*512];                // concat of maxpooled x1..x4
__device__ float g_h5[P2*256];
__device__ float g_h6[P2*1024];
__device__ float g_psum[640*1024];
__device__ float g_psq[640*1024];
__device__ float g_scale[1024];
__device__ float g_shift[1024];

// ---------------- transpose + squared norm ----------------
__global__ void k_transpose(const float* __restrict__ x) {
    int b = blockIdx.x;
    int n = blockIdx.y * 256 + threadIdx.x;
    float ss = 0.f;
    int obase = (b*NPTS + n)*DPAD;
    #pragma unroll 4
    for (int d = 0; d < DIN; d++) {
        float v = x[(b*DIN + d)*NPTS + n];
        g_xt[obase + d] = v;
        ss += v*v;
    }
    #pragma unroll
    for (int d = DIN; d < DPAD; d++) g_xt[obase + d] = 0.f;
    g_xx[b*NPTS + n] = ss;
}

// ---------------- knn: 16 queries/block, tiled over 64 candidates ----------------
extern __shared__ float s_knn[];
__global__ __launch_bounds__(256) void k_knn() {
    int bb = blockIdx.y;
    int q0 = blockIdx.x * 16;
    float* qs  = s_knn;                 // 16*64
    float* xxq = s_knn + 1024;          // 16
    float* pd  = s_knn + 1040;          // 16*1024
    float* cs  = s_knn + 1040 + 16384;  // 64*68 (padded stride)
    int tid = threadIdx.x;

    { // load 16 query rows (1024 floats)
        const float4* src = (const float4*)(g_xt + (bb*NPTS + q0)*DPAD);
        ((float4*)qs)[tid] = src[tid];
    }
    if (tid < 16) xxq[tid] = g_xx[bb*NPTS + q0 + tid];
    __syncthreads();

    int qi0 = (tid >> 5) << 1;   // 0..14
    int mi0 = (tid & 31) << 1;   // 0..62

    for (int t = 0; t < NPTS/64; t++) {
        int m0 = t*64;
        { // load 64x64 candidate tile into padded smem
            const float4* src = (const float4*)(g_xt + (bb*NPTS + m0)*DPAD);
            #pragma unroll
            for (int j = 0; j < 4; j++) {
                int i = tid + 256*j;
                int row = i >> 4, col = i & 15;
                float4 v = src[row*16 + col];
                float* dr = cs + row*68 + col*4;
                dr[0]=v.x; dr[1]=v.y; dr[2]=v.z; dr[3]=v.w;
            }
        }
        __syncthreads();
        float a00=0,a01=0,a10=0,a11=0;
        #pragma unroll
        for (int d4 = 0; d4 < 16; d4++) {
            float4 qa = *(const float4*)(qs + qi0*64 + d4*4);
            float4 qb = *(const float4*)(qs + (qi0+1)*64 + d4*4);
            float4 ca = *(const float4*)(cs + mi0*68 + d4*4);
            float4 cb = *(const float4*)(cs + (mi0+1)*68 + d4*4);
            a00 += qa.x*ca.x + qa.y*ca.y + qa.z*ca.z + qa.w*ca.w;
            a01 += qa.x*cb.x + qa.y*cb.y + qa.z*cb.z + qa.w*cb.w;
            a10 += qb.x*ca.x + qb.y*ca.y + qb.z*ca.z + qb.w*ca.w;
            a11 += qb.x*cb.x + qb.y*cb.y + qb.z*cb.z + qb.w*cb.w;
        }
        float xc0 = g_xx[bb*NPTS + m0 + mi0];
        float xc1 = g_xx[bb*NPTS + m0 + mi0 + 1];
        pd[(qi0  )*NPTS + m0 + mi0    ] = 2.f*a00 - xxq[qi0  ] - xc0;
        pd[(qi0  )*NPTS + m0 + mi0 + 1] = 2.f*a01 - xxq[qi0  ] - xc1;
        pd[(qi0+1)*NPTS + m0 + mi0    ] = 2.f*a10 - xxq[qi0+1] - xc0;
        pd[(qi0+1)*NPTS + m0 + mi0 + 1] = 2.f*a11 - xxq[qi0+1] - xc1;
        __syncthreads();
    }

    // top-20 selection: warp w handles queries 2w, 2w+1
    int w = tid >> 5, lane = tid & 31;
    for (int t = 0; t < 2; t++) {
        int qi = w*2 + t;
        float* row = pd + qi*NPTS;
        for (int it = 0; it < KNN; it++) {
            float best = -FLT_MAX; int bi = NPTS;
            for (int m = lane; m < NPTS; m += 32) {
                float v = row[m];
                if (v > best) { best = v; bi = m; }
            }
            #pragma unroll
            for (int off = 16; off; off >>= 1) {
                float ov = __shfl_down_sync(0xffffffffu, best, off);
                int   oi = __shfl_down_sync(0xffffffffu, bi,   off);
                if (ov > best || (ov == best && oi < bi)) { best = ov; bi = oi; }
            }
            bi = __shfl_sync(0xffffffffu, bi, 0);
            if (lane == 0) {
                g_idx[(bb*NPTS + q0 + qi)*KNN + it] = bi;
                row[bi] = -FLT_MAX;
            }
            __syncwarp();
        }
    }
}

// ---------------- graph-feature gather (120 ch, padded to 128) ----------------
__global__ void k_gather() {
    int bn = blockIdx.x;          // 0..8191
    int tid = threadIdx.x;        // 128
    __shared__ float xn[64];
    __shared__ int idxs[KNN];
    if (tid < 64) xn[tid] = g_xt[bn*DPAD + tid];
    if (tid < KNN) idxs[tid] = g_idx[bn*KNN + tid];
    __syncthreads();
    int b = bn >> 10;
    for (int kk = 0; kk < KNN; kk++) {
        int m = idxs[kk];
        int p = (bn*KNN + kk)*128;
        float v;
        if (tid < 60)       v = g_xt[(b*NPTS + m)*DPAD + tid] - xn[tid];
        else if (tid < 120) v = xn[tid - 60];
        else                v = 0.f;
        g_f0[p + tid] = v;
    }
}

__global__ void k_padw1(const float* __restrict__ w1) {
    int o = blockIdx.x, c = threadIdx.x;
    g_w1p[o*128 + c] = (c < 120) ? w1[o*120 + c] : 0.f;
}

// ---------------- generic fp32 GEMM: C[M,N] = A[M,K] * W[N,K]^T + bias ----------------
__global__ __launch_bounds__(256) void k_gemm(const float* __restrict__ A,
                                              const float* __restrict__ W,
                                              const float* __restrict__ bias,
                                              float* __restrict__ C,
                                              int M, int N, int K) {
    __shared__ float As[16][68];
    __shared__ float Ws[16][68];
    int tid = threadIdx.x;
    int m0 = blockIdx.x * 64, n0 = blockIdx.y * 64;
    int lr = tid >> 2;            // 0..63
    int lk = (tid & 3) * 4;       // 0,4,8,12
    int tm = (tid >> 4) * 4;
    int tn = (tid & 15) * 4;
    float acc[4][4] = {};
    for (int k0 = 0; k0 < K; k0 += 16) {
        float4 av = *(const float4*)(A + (m0+lr)*K + k0 + lk);
        float4 wv = *(const float4*)(W + (n0+lr)*K + k0 + lk);
        As[lk+0][lr]=av.x; As[lk+1][lr]=av.y; As[lk+2][lr]=av.z; As[lk+3][lr]=av.w;
        Ws[lk+0][lr]=wv.x; Ws[lk+1][lr]=wv.y; Ws[lk+2][lr]=wv.z; Ws[lk+3][lr]=wv.w;
        __syncthreads();
        #pragma unroll
        for (int k = 0; k < 16; k++) {
            float4 a = *(const float4*)&As[k][tm];
            float4 b = *(const float4*)&Ws[k][tn];
            acc[0][0] += a.x*b.x; acc[0][1] += a.x*b.y; acc[0][2] += a.x*b.z; acc[0][3] += a.x*b.w;
            acc[1][0] += a.y*b.x; acc[1][1] += a.y*b.y; acc[1][2] += a.y*b.z; acc[1][3] += a.y*b.w;
            acc[2][0] += a.z*b.x; acc[2][1] += a.z*b.y; acc[2][2] += a.z*b.z; acc[2][3] += a.z*b.w;
            acc[3][0] += a.w*b.x; acc[3][1] += a.w*b.y; acc[3][2] += a.w*b.z; acc[3][3] += a.w*b.w;
        }
        __syncthreads();
    }
    float4 bv = *(const float4*)(bias + n0 + tn);
    #pragma unroll
    for (int i = 0; i < 4; i++) {
        float4 o;
        o.x = acc[i][0] + bv.x; o.y = acc[i][1] + bv.y;
        o.z = acc[i][2] + bv.z; o.w = acc[i][3] + bv.w;
        *(float4*)(C + (m0+tm+i)*N + n0 + tn) = o;
    }
}

// ---------------- BN stats: deterministic two-stage ----------------
__global__ void k_stats1(const float* __restrict__ h, int M, int C) {
    int c = blockIdx.y*256 + threadIdx.x;
    if (c >= C) return;
    int r0 = blockIdx.x * 256;
    float s = 0.f, q = 0.f;
    for (int r = 0; r < 256; r++) {
        float v = h[(r0 + r)*C + c];
        s += v; q += v*v;
    }
    g_psum[blockIdx.x*C + c] = s;
    g_psq [blockIdx.x*C + c] = q;
}

__global__ void k_stats2(const float* __restrict__ gam, const float* __restrict__ bet,
                         int C, int nb, float invM) {
    int c = threadIdx.x;
    if (c >= C) return;
    float s = 0.f, q = 0.f;
    for (int i = 0; i < nb; i++) { s += g_psum[i*C + c]; q += g_psq[i*C + c]; }
    float mean = s * invM;
    float var  = q * invM - mean*mean;
    float sc = gam[c] * rsqrtf(var + BN_EPS);
    g_scale[c] = sc;
    g_shift[c] = bet[c] - mean*sc;
}

// ---------------- normalize + lrelu + maxpool over k ----------------
__global__ void k_normpool(float* __restrict__ h, int C, int off) {
    int bn = blockIdx.x;
    int c = threadIdx.x;
    float sc = g_scale[c], sh = g_shift[c];
    float mx = -FLT_MAX;
    int base = bn*KNN*C + c;
    #pragma unroll 4
    for (int kk = 0; kk < KNN; kk++) {
        float v = h[base + kk*C] * sc + sh;
        v = (v >= 0.f) ? v : SLOPE*v;
        h[base + kk*C] = v;
        mx = fmaxf(mx, v);
    }
    g_xc[bn*512 + off + c] = mx;
}

__global__ void k_norm(float* __restrict__ h, int total, int Cmask) {
    int i = blockIdx.x*256 + threadIdx.x;
    if (i >= total) return;
    int c = i & Cmask;
    float v = h[i]*g_scale[c] + g_shift[c];
    h[i] = (v >= 0.f) ? v : SLOPE*v;
}

__global__ void k_normout(const float* __restrict__ h, float* __restrict__ out,
                          int total, int Cmask) {
    int i = blockIdx.x*256 + threadIdx.x;
    if (i >= total) return;
    int c = i & Cmask;
    float v = h[i]*g_scale[c] + g_shift[c];
    out[i] = (v >= 0.f) ? v : SLOPE*v;
}

// ---------------- launch ----------------
extern "C" void kernel_launch(void* const* d_in, const int* in_sizes, int n_in,
                              void* d_out, int out_size) {
    const float* x  = (const float*)d_in[0];
    const float* w[7]; const float* bi[7]; const float* ga[7]; const float* be[7];
    for (int i = 1; i <= 6; i++) {
        w [i] = (const float*)d_in[1 + 4*(i-1) + 0];
        bi[i] = (const float*)d_in[1 + 4*(i-1) + 1];
        ga[i] = (const float*)d_in[1 + 4*(i-1) + 2];
        be[i] = (const float*)d_in[1 + 4*(i-1) + 3];
    }
    float* out = (float*)d_out;

    float *f0, *w1p, *h1, *h2, *h3, *h4, *xc, *h5, *h6;
    cudaGetSymbolAddress((void**)&f0,  g_f0);
    cudaGetSymbolAddress((void**)&w1p, g_w1p);
    cudaGetSymbolAddress((void**)&h1,  g_h1);
    cudaGetSymbolAddress((void**)&h2,  g_h2);
    cudaGetSymbolAddress((void**)&h3,  g_h3);
    cudaGetSymbolAddress((void**)&h4,  g_h4);
    cudaGetSymbolAddress((void**)&xc,  g_xc);
    cudaGetSymbolAddress((void**)&h5,  g_h5);
    cudaGetSymbolAddress((void**)&h6,  g_h6);

    const int knn_smem = (1024 + 16 + 16384 + 64*68) * 4;  // 87104 B
    cudaFuncSetAttribute(k_knn, cudaFuncAttributeMaxDynamicSharedMemorySize, knn_smem);

    k_transpose<<<dim3(BATCH, 4), 256>>>(x);
    k_knn<<<dim3(NPTS/16, BATCH), 256, knn_smem>>>();
    k_gather<<<P2, 128>>>();
    k_padw1<<<64, 128>>>(w[1]);

    // layers 1-4 on P1 points
    struct { const float* A; const float* W; float* H; int N; int K; int off; int li; } L4d[4] = {
        { f0, w1p, h1,  64, 128,   0, 1 },
        { h1, w[2], h2, 64,  64,  64, 2 },
        { h2, w[3], h3, 128, 64, 128, 3 },
        { h3, w[4], h4, 256,128, 256, 4 },
    };
    for (int i = 0; i < 4; i++) {
        int N = L4d[i].N, K = L4d[i].K, li = L4d[i].li;
        k_gemm<<<dim3(P1/64, N/64), 256>>>(L4d[i].A, L4d[i].W, bi[li], L4d[i].H, P1, N, K);
        k_stats1<<<dim3(P1/256, 1), 256>>>(L4d[i].H, P1, N);
        k_stats2<<<1, N>>>(ga[li], be[li], N, P1/256, 1.f/(float)P1);
        k_normpool<<<P2, N>>>(L4d[i].H, N, L4d[i].off);
    }

    // layer 5: 512 -> 256 on P2 points
    k_gemm<<<dim3(P2/64, 256/64), 256>>>(xc, w[5], bi[5], h5, P2, 256, 512);
    k_stats1<<<dim3(P2/256, 1), 256>>>(h5, P2, 256);
    k_stats2<<<1, 256>>>(ga[5], be[5], 256, P2/256, 1.f/(float)P2);
    k_norm<<<(P2*256)/256, 256>>>(h5, P2*256, 255);

    // layer 6: 256 -> 1024 on P2 points, output (B,N,1024)
    k_gemm<<<dim3(P2/64, 1024/64), 256>>>(h5, w[6], bi[6], h6, P2, 1024, 256);
    k_stats1<<<dim3(P2/256, 4), 256>>>(h6, P2, 1024);
    k_stats2<<<1, 1024>>>(ga[6], be[6], 1024, P2/256, 1.f/(float)P2);
    k_normout<<<(P2*1024)/256, 256>>>(h6, out, P2*1024, 1023);
}